// round 3
// baseline (speedup 1.0000x reference)
#include <cuda_runtime.h>
#include <cuda_bf16.h>

// Problem: durations [B=32, T=512] fp32, max_len=4096.
// repeats = (int)(d + 0.5)  (d in [1,8) so repeats in 1..8)
// ends = inclusive cumsum(repeats); starts = ends - repeats
// out[b, t, j] = 1.0f iff starts[b,j] <= t < ends[b,j], else 0.
// Output [B, max_len, T] fp32 = 256 MiB. At most one 1 per (b,t) row.
//
// Strategy: memset the 256 MiB to zero (bandwidth-optimal driver memset),
// then scatter the ~74K ones with a tiny kernel (one block per batch,
// one thread per text token, shared-memory inclusive scan).

#define B_BATCH 32
#define T_TEXT  512
#define MAX_LEN 4096

__global__ void lr_scatter_kernel(const float* __restrict__ durations,
                                  float* __restrict__ out)
{
    const int b = blockIdx.x;   // 0..31
    const int j = threadIdx.x;  // 0..511

    __shared__ int s[T_TEXT];

    // repeats = truncate(d + 0.5) ; d > 0 so truncation == the reference cast
    const float d = durations[b * T_TEXT + j];
    const int rep = (int)(d + 0.5f);

    s[j] = rep;
    __syncthreads();

    // Hillis-Steele inclusive scan over 512 elements
    #pragma unroll
    for (int off = 1; off < T_TEXT; off <<= 1) {
        int v = (j >= off) ? s[j - off] : 0;
        __syncthreads();
        s[j] += v;
        __syncthreads();
    }

    int end   = s[j];
    int start = end - rep;

    if (end > MAX_LEN) end = MAX_LEN;

    float* base = out + (size_t)b * MAX_LEN * T_TEXT + j;
    for (int t = start; t < end; ++t) {
        base[(size_t)t * T_TEXT] = 1.0f;
    }
}

extern "C" void kernel_launch(void* const* d_in, const int* in_sizes, int n_in,
                              void* d_out, int out_size)
{
    const float* durations = (const float*)d_in[0];
    float* out = (float*)d_out;

    // Zero the whole 256 MiB output (near-peak DRAM write bandwidth).
    cudaMemsetAsync(d_out, 0, (size_t)out_size * sizeof(float), 0);

    // Scatter the ones. Same (default) stream -> ordered after the memset.
    lr_scatter_kernel<<<B_BATCH, T_TEXT>>>(durations, out);
}

// round 4
// speedup vs baseline: 1.0613x; 1.0613x over previous
#include <cuda_runtime.h>
#include <cuda_bf16.h>

// durations [B=32, T=512] fp32, max_len=4096.
// repeats = (int)(d + 0.5); ends = inclusive cumsum; starts = ends - repeats
// out[b, t, j] = (starts[b,j] <= t < ends[b,j]) ? 1 : 0   -> [32, 4096, 512] fp32 (256 MiB)
//
// Single-pass strategy: write every element exactly once with STG.128.
// Kernel A: per-batch inclusive scan -> g_ends (32x512).
// Kernel B: each thread owns a fixed quad of 4 tokens; boundary values are
//           loop-invariant registers; loop over t rows, one float4 store each.

#define B_BATCH 32
#define T_TEXT  512
#define MAX_LEN 4096

#define BLOCKS_PER_BATCH 64
#define ROWS_PER_BLOCK   (MAX_LEN / BLOCKS_PER_BATCH)   // 64
#define FILL_THREADS     512
#define QUADS_PER_ROW    (T_TEXT / 4)                   // 128
#define ROWS_PER_ITER    (FILL_THREADS / QUADS_PER_ROW) // 4
#define ITERS            (ROWS_PER_BLOCK / ROWS_PER_ITER) // 16

__device__ int g_ends[B_BATCH * T_TEXT];

__global__ void lr_scan_kernel(const float* __restrict__ durations)
{
    const int b = blockIdx.x;
    const int j = threadIdx.x;

    __shared__ int s[T_TEXT];

    const float d = durations[b * T_TEXT + j];
    const int rep = (int)(d + 0.5f);   // d > 0: truncation == reference cast

    s[j] = rep;
    __syncthreads();

    #pragma unroll
    for (int off = 1; off < T_TEXT; off <<= 1) {
        int v = (j >= off) ? s[j - off] : 0;
        __syncthreads();
        s[j] += v;
        __syncthreads();
    }

    g_ends[b * T_TEXT + j] = s[j];
}

__global__ __launch_bounds__(FILL_THREADS, 4)
void lr_fill_kernel(float* __restrict__ out)
{
    const int b = blockIdx.y;

    // s[0] = 0, s[1+j] = ends[j]  => start_j = s[j], end_j = s[j+1]
    __shared__ int s[T_TEXT + 1];
    if (threadIdx.x == 0) s[0] = 0;
    if (threadIdx.x < T_TEXT) s[1 + threadIdx.x] = g_ends[b * T_TEXT + threadIdx.x];
    __syncthreads();

    const int q  = threadIdx.x & (QUADS_PER_ROW - 1);  // quad index within row
    const int tr = threadIdx.x >> 7;                   // 0..3 row offset within iter
    const int j0 = q * 4;

    // Loop-invariant token boundaries for this thread's 4 tokens
    const int a0 = s[j0 + 0];
    const int a1 = s[j0 + 1];
    const int a2 = s[j0 + 2];
    const int a3 = s[j0 + 3];
    const int a4 = s[j0 + 4];

    const int t_base = blockIdx.x * ROWS_PER_BLOCK + tr;

    float4* row_base = (float4*)(out + ((size_t)b * MAX_LEN) * T_TEXT) + q;

    #pragma unroll
    for (int it = 0; it < ITERS; ++it) {
        const int t = t_base + it * ROWS_PER_ITER;
        float4 v;
        v.x = (a0 <= t && t < a1) ? 1.0f : 0.0f;
        v.y = (a1 <= t && t < a2) ? 1.0f : 0.0f;
        v.z = (a2 <= t && t < a3) ? 1.0f : 0.0f;
        v.w = (a3 <= t && t < a4) ? 1.0f : 0.0f;
        row_base[(size_t)t * QUADS_PER_ROW] = v;
    }
}

extern "C" void kernel_launch(void* const* d_in, const int* in_sizes, int n_in,
                              void* d_out, int out_size)
{
    const float* durations = (const float*)d_in[0];
    float* out = (float*)d_out;

    lr_scan_kernel<<<B_BATCH, T_TEXT>>>(durations);

    dim3 grid(BLOCKS_PER_BATCH, B_BATCH);
    lr_fill_kernel<<<grid, FILL_THREADS>>>(out);
}

// round 5
// speedup vs baseline: 1.0957x; 1.0324x over previous
#include <cuda_runtime.h>
#include <cuda_bf16.h>

// durations [B=32, T=512] fp32, max_len=4096.
// repeats = (int)(d + 0.5); ends = inclusive cumsum; starts = ends - repeats
// out[b, t, j] = (starts[b,j] <= t < ends[b,j]) ? 1 : 0   -> [32, 4096, 512] fp32 (256 MiB)
//
// ONE fused kernel: every block redundantly computes its batch's 512-element
// scan (warp-shuffle scan, ~300 cycles, inputs L2-resident), then streams its
// 64 rows with STG.128, writing every output element exactly once.

#define B_BATCH 32
#define T_TEXT  512
#define MAX_LEN 4096

#define BLOCKS_PER_BATCH 64
#define ROWS_PER_BLOCK   (MAX_LEN / BLOCKS_PER_BATCH)     // 64
#define FILL_THREADS     512
#define NWARPS           (FILL_THREADS / 32)              // 16
#define QUADS_PER_ROW    (T_TEXT / 4)                     // 128
#define ROWS_PER_ITER    (FILL_THREADS / QUADS_PER_ROW)   // 4
#define ITERS            (ROWS_PER_BLOCK / ROWS_PER_ITER) // 16

__global__ __launch_bounds__(FILL_THREADS, 4)
void lr_fused_kernel(const float* __restrict__ durations,
                     float* __restrict__ out)
{
    const int b   = blockIdx.y;
    const int j   = threadIdx.x;
    const int lane = j & 31;
    const int wrp  = j >> 5;

    // s[0] = 0, s[1+j] = inclusive_cumsum(rep)[j]
    __shared__ int s[T_TEXT + 1];
    __shared__ int wsum[NWARPS];

    // --- scan prologue (redundant per block; inputs are L2-resident) ---
    const float d = durations[b * T_TEXT + j];
    int rep = (int)(d + 0.5f);        // d > 0: truncation == reference cast

    int v = rep;
    #pragma unroll
    for (int off = 1; off < 32; off <<= 1) {
        int n = __shfl_up_sync(0xFFFFFFFFu, v, off);
        if (lane >= off) v += n;
    }
    if (lane == 31) wsum[wrp] = v;
    __syncthreads();

    if (wrp == 0) {
        int wv = (lane < NWARPS) ? wsum[lane] : 0;
        #pragma unroll
        for (int off = 1; off < NWARPS; off <<= 1) {
            int n = __shfl_up_sync(0xFFFFFFFFu, wv, off);
            if (lane >= off) wv += n;
        }
        if (lane < NWARPS) wsum[lane] = wv;
        if (lane == 0) s[0] = 0;
    }
    __syncthreads();

    const int warp_off = (wrp > 0) ? wsum[wrp - 1] : 0;
    s[1 + j] = v + warp_off;
    __syncthreads();

    // --- fill mainloop: each thread owns a fixed quad of 4 tokens ---
    const int q  = j & (QUADS_PER_ROW - 1);   // quad index within row
    const int tr = j >> 7;                    // 0..3 row offset within iter
    const int j0 = q * 4;

    const int a0 = s[j0 + 0];
    const int a1 = s[j0 + 1];
    const int a2 = s[j0 + 2];
    const int a3 = s[j0 + 3];
    const int a4 = s[j0 + 4];

    const int t_base = blockIdx.x * ROWS_PER_BLOCK + tr;

    float4* row_base = (float4*)(out + ((size_t)b * MAX_LEN) * T_TEXT) + q;

    #pragma unroll
    for (int it = 0; it < ITERS; ++it) {
        const int t = t_base + it * ROWS_PER_ITER;
        float4 val;
        val.x = (a0 <= t && t < a1) ? 1.0f : 0.0f;
        val.y = (a1 <= t && t < a2) ? 1.0f : 0.0f;
        val.z = (a2 <= t && t < a3) ? 1.0f : 0.0f;
        val.w = (a3 <= t && t < a4) ? 1.0f : 0.0f;
        row_base[(size_t)t * QUADS_PER_ROW] = val;
    }
}

extern "C" void kernel_launch(void* const* d_in, const int* in_sizes, int n_in,
                              void* d_out, int out_size)
{
    const float* durations = (const float*)d_in[0];
    float* out = (float*)d_out;

    dim3 grid(BLOCKS_PER_BATCH, B_BATCH);
    lr_fused_kernel<<<grid, FILL_THREADS>>>(durations, out);
}

// round 7
// speedup vs baseline: 1.1113x; 1.0142x over previous
#include <cuda_runtime.h>
#include <cuda_bf16.h>

// durations [B=32, T=512] fp32, max_len=4096.
// repeats = (int)(d + 0.5); ends = inclusive cumsum; starts = ends - repeats
// out[b, t, j] = (starts[b,j] <= t < ends[b,j]) ? 1 : 0   -> [32, 4096, 512] fp32 (256 MiB)
//
// ONE fused kernel, write-only streaming:
//  - every block redundantly computes its batch's 512-element scan
//    (warp-shuffle scan, ~300 cyc, inputs L2-resident)
//  - then streams 128 rows with evict-first STG.128 (__stcs), each output
//    element written exactly once.
// grid = 1024 (32 rows-groups x 32 batches) -> fewer wave transitions than 2048.

#define B_BATCH 32
#define T_TEXT  512
#define MAX_LEN 4096

#define BLOCKS_PER_BATCH 32
#define ROWS_PER_BLOCK   (MAX_LEN / BLOCKS_PER_BATCH)     // 128
#define FILL_THREADS     512
#define NWARPS           (FILL_THREADS / 32)              // 16
#define QUADS_PER_ROW    (T_TEXT / 4)                     // 128
#define ROWS_PER_ITER    (FILL_THREADS / QUADS_PER_ROW)   // 4
#define ITERS            (ROWS_PER_BLOCK / ROWS_PER_ITER) // 32

__global__ __launch_bounds__(FILL_THREADS, 4)
void lr_fused_kernel(const float* __restrict__ durations,
                     float* __restrict__ out)
{
    const int b    = blockIdx.y;
    const int j    = threadIdx.x;
    const int lane = j & 31;
    const int wrp  = j >> 5;

    // s[0] = 0, s[1+j] = inclusive_cumsum(rep)[j]
    __shared__ int s[T_TEXT + 1];
    __shared__ int wsum[NWARPS];

    // --- scan prologue (redundant per block; inputs L2-resident) ---
    const float d = durations[b * T_TEXT + j];
    const int rep = (int)(d + 0.5f);   // d > 0: truncation == reference cast

    int v = rep;
    #pragma unroll
    for (int off = 1; off < 32; off <<= 1) {
        int n = __shfl_up_sync(0xFFFFFFFFu, v, off);
        if (lane >= off) v += n;
    }
    if (lane == 31) wsum[wrp] = v;
    __syncthreads();

    if (wrp == 0) {
        int wv = (lane < NWARPS) ? wsum[lane] : 0;
        #pragma unroll
        for (int off = 1; off < NWARPS; off <<= 1) {
            int n = __shfl_up_sync(0xFFFFFFFFu, wv, off);
            if (lane >= off) wv += n;
        }
        if (lane < NWARPS) wsum[lane] = wv;
        if (lane == 0) s[0] = 0;
    }
    __syncthreads();

    const int warp_off = (wrp > 0) ? wsum[wrp - 1] : 0;
    s[1 + j] = v + warp_off;
    __syncthreads();

    // --- fill mainloop: each thread owns a fixed quad of 4 tokens ---
    const int q  = j & (QUADS_PER_ROW - 1);   // quad index within row
    const int tr = j >> 7;                    // 0..3 row offset within iter
    const int j0 = q * 4;

    const int a0 = s[j0 + 0];
    const int a1 = s[j0 + 1];
    const int a2 = s[j0 + 2];
    const int a3 = s[j0 + 3];
    const int a4 = s[j0 + 4];

    const int t_base = blockIdx.x * ROWS_PER_BLOCK + tr;

    float4* row_base = (float4*)(out + ((size_t)b * MAX_LEN) * T_TEXT) + q;

    #pragma unroll
    for (int it = 0; it < ITERS; ++it) {
        const int t = t_base + it * ROWS_PER_ITER;
        float4 val;
        val.x = (a0 <= t && t < a1) ? 1.0f : 0.0f;
        val.y = (a1 <= t && t < a2) ? 1.0f : 0.0f;
        val.z = (a2 <= t && t < a3) ? 1.0f : 0.0f;
        val.w = (a3 <= t && t < a4) ? 1.0f : 0.0f;
        // evict-first streaming store: write-once data, keep L2 drained
        __stcs(&row_base[(size_t)t * QUADS_PER_ROW], val);
    }
}

extern "C" void kernel_launch(void* const* d_in, const int* in_sizes, int n_in,
                              void* d_out, int out_size)
{
    const float* durations = (const float*)d_in[0];
    float* out = (float*)d_out;

    dim3 grid(BLOCKS_PER_BATCH, B_BATCH);
    lr_fused_kernel<<<grid, FILL_THREADS>>>(durations, out);
}